// round 6
// baseline (speedup 1.0000x reference)
#include <cuda_runtime.h>

// Problem constants
#define NUc 32768
#define NIc 8192
#define Nc  40960          // NU + NI
#define Ec  2000000        // undirected edges
#define E2c (2 * Ec)       // directed edges
#define NE_MM  163840
#define NE_IMG 81920
#define NE_TXT 81920

// ---------------- scratch (device globals; no allocation allowed) ----------------
__device__ int   g_eu[Ec];
__device__ int   g_ev[Ec];
__device__ int   g_cnt[Nc];          // in-degree counts (base degree)
__device__ int   g_rowptr[Nc + 1];
__device__ int   g_fill[Nc];
__device__ int   g_csr_src[E2c];
__device__ int   g_csr_eid[E2c];
__device__ float g_csr_w[E2c];       // per-layer edge weights (dinv[src]*mask)
__device__ float g_maskf[Ec];
__device__ float g_dinv[Nc];
__device__ int   g_flag[4];

__device__ float g_vemb[NIc * 64];
__device__ float g_temb[NIc * 64];
__device__ float g_hmm [NIc * 64];
__device__ float g_h1  [NIc * 64];
__device__ float g_h2  [NIc * 64];

__device__ float g_ego [Nc * 64];
__device__ float g_next[Nc * 64];
__device__ float g_hbuf[Nc * 64];
__device__ float g_acc [Nc * 64];

// Vectorized fire-and-forget atomic add (sm_90+) — only the small KNN SPMMs
__device__ __forceinline__ void red4(float* p, float a, float b, float c, float d) {
    asm volatile("red.global.add.v4.f32 [%0], {%1,%2,%3,%4};"
                 :: "l"(p), "f"(a), "f"(b), "f"(c), "f"(d) : "memory");
}

// ---------------- dtype detection: int64 vs int32 index arrays ----------------
// If data is int32, reading pairs as int64 yields values with nonzero high
// words -> out of [0, limit). 512 slots scanned; misdetection probability ~0.
__global__ void k_detect(const void* p, int cnt, long long limit, int slot) {
    __shared__ int bad;
    if (threadIdx.x == 0) bad = 0;
    __syncthreads();
    const long long* q = (const long long*)p;
    for (int i = threadIdx.x; i < cnt; i += blockDim.x) {
        long long v = q[i];
        if (v < 0 || v >= limit) atomicOr(&bad, 1);
    }
    __syncthreads();
    if (threadIdx.x == 0) g_flag[slot] = bad;   // 1 => int32, 0 => int64
}

__global__ void k_zero_f32(float* p, int n) {
    int i = blockIdx.x * blockDim.x + threadIdx.x;
    if (i < n) p[i] = 0.0f;
}
__global__ void k_zero_i32(int* p, int n) {
    int i = blockIdx.x * blockDim.x + threadIdx.x;
    if (i < n) p[i] = 0;
}

// ---------------- edge conversion + in-degree counting (both directions) ----------------
__global__ void k_convert(const void* p) {
    int i = blockIdx.x * blockDim.x + threadIdx.x;
    if (i >= Ec) return;
    int eu, ev;
    if (g_flag[0]) {
        const int* q = (const int*)p;
        eu = q[i]; ev = q[Ec + i];
    } else {
        const long long* q = (const long long*)p;
        eu = (int)q[i]; ev = (int)q[Ec + i];
    }
    g_eu[i] = eu; g_ev[i] = ev;
    atomicAdd(&g_cnt[eu], 1);
    atomicAdd(&g_cnt[ev], 1);
}

// ---------------- single-block exclusive scan over g_cnt -> g_rowptr ----------------
__global__ void k_scan() {
    __shared__ int warpsum[32];
    __shared__ int s_carry;
    int tid = threadIdx.x, lane = tid & 31, wid = tid >> 5;
    if (tid == 0) { s_carry = 0; g_rowptr[0] = 0; }
    __syncthreads();
    for (int base = 0; base < Nc; base += 1024) {
        int i = base + tid;
        int v = (i < Nc) ? g_cnt[i] : 0;
        int x = v;
#pragma unroll
        for (int o = 1; o < 32; o <<= 1) {
            int y = __shfl_up_sync(0xffffffffu, x, o);
            if (lane >= o) x += y;
        }
        if (lane == 31) warpsum[wid] = x;
        __syncthreads();
        if (wid == 0) {
            int s = warpsum[lane];
#pragma unroll
            for (int o = 1; o < 32; o <<= 1) {
                int y = __shfl_up_sync(0xffffffffu, s, o);
                if (lane >= o) s += y;
            }
            warpsum[lane] = s;
        }
        __syncthreads();
        int off = (wid > 0) ? warpsum[wid - 1] : 0;
        int incl = x + off + s_carry;
        if (i < Nc) g_rowptr[i + 1] = incl;
        __syncthreads();
        if (tid == 1023) s_carry = incl;
        __syncthreads();
    }
}

__global__ void k_copy_fill() {
    int i = blockIdx.x * blockDim.x + threadIdx.x;
    if (i < Nc) g_fill[i] = g_rowptr[i];
}

// ---------------- CSR fill: each undirected edge contributes both directions ----------------
__global__ void k_fill() {
    int e = blockIdx.x * blockDim.x + threadIdx.x;
    if (e >= Ec) return;
    int eu = g_eu[e], ev = g_ev[e];
    int p1 = atomicAdd(&g_fill[ev], 1);
    g_csr_src[p1] = eu; g_csr_eid[p1] = e;
    int p2 = atomicAdd(&g_fill[eu], 1);
    g_csr_src[p2] = ev; g_csr_eid[p2] = e;
}

// ---------------- GEMM: C[M x 64] = A[M x K] * B[64 x K]^T (+bias) ----------------
__global__ __launch_bounds__(256) void k_gemm64(
        const float* __restrict__ A, const float* __restrict__ B,
        const float* __restrict__ bias, float* __restrict__ C, int K) {
    __shared__ float As[64][33];
    __shared__ float Bs[64][33];
    const int tx = threadIdx.x & 15;
    const int ty = threadIdx.x >> 4;
    const int rowBase = blockIdx.x * 64;
    float acc[4][4] = {};
    for (int k0 = 0; k0 < K; k0 += 32) {
#pragma unroll
        for (int it = 0; it < 2; it++) {
            int lin = threadIdx.x + it * 256;
            int r = lin >> 3, c4 = lin & 7;
            float4 va = *(const float4*)(A + (size_t)(rowBase + r) * K + k0 + c4 * 4);
            As[r][c4 * 4 + 0] = va.x; As[r][c4 * 4 + 1] = va.y;
            As[r][c4 * 4 + 2] = va.z; As[r][c4 * 4 + 3] = va.w;
            float4 vb = *(const float4*)(B + (size_t)r * K + k0 + c4 * 4);
            Bs[r][c4 * 4 + 0] = vb.x; Bs[r][c4 * 4 + 1] = vb.y;
            Bs[r][c4 * 4 + 2] = vb.z; Bs[r][c4 * 4 + 3] = vb.w;
        }
        __syncthreads();
#pragma unroll
        for (int kk = 0; kk < 32; kk++) {
            float a[4], b[4];
#pragma unroll
            for (int i = 0; i < 4; i++) a[i] = As[ty * 4 + i][kk];
#pragma unroll
            for (int j = 0; j < 4; j++) b[j] = Bs[tx * 4 + j][kk];
#pragma unroll
            for (int i = 0; i < 4; i++)
#pragma unroll
                for (int j = 0; j < 4; j++) acc[i][j] = fmaf(a[i], b[j], acc[i][j]);
        }
        __syncthreads();
    }
#pragma unroll
    for (int i = 0; i < 4; i++)
#pragma unroll
        for (int j = 0; j < 4; j++) {
            float v = acc[i][j];
            if (bias) v += bias[tx * 4 + j];
            C[(size_t)(rowBase + ty * 4 + i) * 64 + tx * 4 + j] = v;
        }
}

// ---------------- SPMM for KNN graphs: out[row] += val * h[col] ----------------
__global__ void k_spmm(const void* idxp, const float* __restrict__ vals,
                       const float* __restrict__ hin, float* __restrict__ out,
                       int ne, int slot) {
    long long t = (long long)blockIdx.x * blockDim.x + threadIdx.x;
    int e = (int)(t >> 4);
    if (e >= ne) return;
    int c = (int)(t & 15);
    int r, ci;
    if (g_flag[slot]) {
        const int* q = (const int*)idxp; r = q[e]; ci = q[ne + e];
    } else {
        const long long* q = (const long long*)idxp; r = (int)q[e]; ci = (int)q[ne + e];
    }
    float v = vals[e];
    float4 x = __ldg((const float4*)(hin + (size_t)ci * 64) + c);
    red4(out + (size_t)r * 64 + c * 4, v * x.x, v * x.y, v * x.z, v * x.w);
}

// ---------------- row-wise L2 normalization (warp per row) ----------------
__global__ void k_l2norm(float* __restrict__ x, int rows) {
    int w = (blockIdx.x * blockDim.x + threadIdx.x) >> 5;
    if (w >= rows) return;
    int lane = threadIdx.x & 31;
    float2 v = ((float2*)(x + (size_t)w * 64))[lane];
    float s = v.x * v.x + v.y * v.y;
#pragma unroll
    for (int o = 16; o; o >>= 1) s += __shfl_xor_sync(0xffffffffu, s, o);
    float sc = 1.0f / fmaxf(sqrtf(s), 1e-12f);
    v.x *= sc; v.y *= sc;
    ((float2*)(x + (size_t)w * 64))[lane] = v;
}

// ---------------- propagation ----------------
__global__ void k_init_ego(const float* __restrict__ ue, const float* __restrict__ it) {
    int i = blockIdx.x * blockDim.x + threadIdx.x;
    if (i >= Nc * 64) return;
    float v = (i < NUc * 64) ? ue[i] : it[i - NUc * 64];
    g_ego[i] = v;
    g_acc[i] = v;
}

// 16 lanes per edge, float4 lanes: maskf[e] = (dot(ego[eu], ego[ev]) >= 0)
__global__ __launch_bounds__(256) void k_mask(const float* __restrict__ ego) {
    int t = blockIdx.x * blockDim.x + threadIdx.x;
    int e = t >> 4;
    if (e >= Ec) return;
    int sub = threadIdx.x & 15;
    int a = g_eu[e], b = g_ev[e];
    float4 x = __ldg((const float4*)(ego + (size_t)a * 64) + sub);
    float4 y = __ldg((const float4*)(ego + (size_t)b * 64) + sub);
    float s = x.x * y.x + x.y * y.y + x.z * y.z + x.w * y.w;
#pragma unroll
    for (int o = 8; o; o >>= 1) s += __shfl_xor_sync(0xffffffffu, s, o);
    if (sub == 0) g_maskf[e] = (s >= 0.0f) ? 1.0f : 0.0f;
}

// warp per node: dinv from CSR row (filtered: sum of mask; else: row length)
__global__ void k_dinv_csr(int filtered) {
    int n = (blockIdx.x * blockDim.x + threadIdx.x) >> 5;
    if (n >= Nc) return;
    int lane = threadIdx.x & 31;
    int s = g_rowptr[n], e = g_rowptr[n + 1];
    float d;
    if (filtered) {
        d = 0.0f;
        for (int i = s + lane; i < e; i += 32) d += g_maskf[g_csr_eid[i]];
#pragma unroll
        for (int o = 16; o; o >>= 1) d += __shfl_xor_sync(0xffffffffu, d, o);
    } else {
        d = (float)(e - s);
    }
    if (lane == 0) g_dinv[n] = rsqrtf(d + 1.0f);
}

// per-layer CSR edge weights: w[i] = dinv[src]*mask  (coalesced writes; random
// reads hit small L1/L2-resident tables). Keeps random sector traffic out of
// the gather hot loop.
__global__ void k_edge_w(int filtered) {
    int i = blockIdx.x * blockDim.x + threadIdx.x;
    if (i >= E2c) return;
    float w = g_dinv[g_csr_src[i]];
    if (filtered) w *= g_maskf[g_csr_eid[i]];
    g_csr_w[i] = w;
}

// Fused GCN layer: warp per dst node (8-way interleaved for wave balance).
// next[n] = dinv[n]*sum_edges(w*h[src]) + h[n]*dinv[n]^2 + b ;  acc += next
__global__ __launch_bounds__(256) void k_gcn_gather(
        const float* __restrict__ bvec, float* __restrict__ next) {
    int w = (blockIdx.x * blockDim.x + threadIdx.x) >> 5;
    if (w >= Nc) return;
    int n = ((w & 7) * (Nc / 8)) + (w >> 3);   // interleave users/items per wave
    int lane = threadIdx.x & 31;
    int s = g_rowptr[n], e = g_rowptr[n + 1];
    float ax0 = 0.0f, ay0 = 0.0f, ax1 = 0.0f, ay1 = 0.0f;
    int base = s;
    // fast path: full groups of 32 edges, 8-way MLP batches, dual accumulators
    for (; base + 32 <= e; base += 32) {
        int idx = base + lane;
        int   src = g_csr_src[idx];
        float wgt = g_csr_w[idx];
#pragma unroll
        for (int j0 = 0; j0 < 32; j0 += 8) {
            float wj[8]; int sj[8]; float2 hv[8];
#pragma unroll
            for (int j = 0; j < 8; j++) {
                wj[j] = __shfl_sync(0xffffffffu, wgt, j0 + j);
                sj[j] = __shfl_sync(0xffffffffu, src, j0 + j);
            }
#pragma unroll
            for (int j = 0; j < 8; j++) {
                hv[j] = make_float2(0.0f, 0.0f);
                if (wj[j] != 0.0f)
                    hv[j] = __ldg((const float2*)(g_hbuf + (size_t)sj[j] * 64) + lane);
            }
#pragma unroll
            for (int j = 0; j < 8; j += 2) {
                ax0 = fmaf(wj[j],     hv[j].x,     ax0);
                ay0 = fmaf(wj[j],     hv[j].y,     ay0);
                ax1 = fmaf(wj[j + 1], hv[j + 1].x, ax1);
                ay1 = fmaf(wj[j + 1], hv[j + 1].y, ay1);
            }
        }
    }
    // tail
    if (base < e) {
        int idx = base + lane;
        int   src = 0; float wgt = 0.0f;
        if (idx < e) { src = g_csr_src[idx]; wgt = g_csr_w[idx]; }
        int cnt = e - base;
        for (int j = 0; j < cnt; j++) {
            float wj = __shfl_sync(0xffffffffu, wgt, j);
            int   sj = __shfl_sync(0xffffffffu, src, j);
            if (wj != 0.0f) {
                float2 hv = __ldg((const float2*)(g_hbuf + (size_t)sj * 64) + lane);
                ax0 = fmaf(wj, hv.x, ax0);
                ay0 = fmaf(wj, hv.y, ay0);
            }
        }
    }
    float ax = ax0 + ax1, ay = ay0 + ay1;
    float di = g_dinv[n];
    float2 hs = ((const float2*)(g_hbuf + (size_t)n * 64))[lane];
    float2 bb = ((const float2*)bvec)[lane];
    float2 nx;
    nx.x = ax * di + hs.x * di * di + bb.x;
    nx.y = ay * di + hs.y * di * di + bb.y;
    ((float2*)(next + (size_t)n * 64))[lane] = nx;
    float2* ap = (float2*)(g_acc + (size_t)n * 64) + lane;
    float2 av = *ap;
    av.x += nx.x; av.y += nx.y;
    *ap = av;
}

// out[n, colbase + d] = acc/3 (+ per-item addend for item rows)
__global__ void k_writer(const float* __restrict__ addbuf, float* __restrict__ out, int colbase) {
    int i = blockIdx.x * blockDim.x + threadIdx.x;
    if (i >= Nc * 64) return;
    int n = i >> 6, d = i & 63;
    float v = g_acc[i] * (1.0f / 3.0f);
    if (addbuf && n >= NUc) v += addbuf[(size_t)(n - NUc) * 64 + d];
    out[(size_t)n * 192 + colbase + d] = v;
}

// ---------------- host ----------------
extern "C" void kernel_launch(void* const* d_in, const int* in_sizes, int n_in,
                              void* d_out, int out_size) {
    const float* user  = (const float*)d_in[0];
    const float* item  = (const float*)d_in[1];
    const float* vfeat = (const float*)d_in[2];
    const float* tfeat = (const float*)d_in[3];
    const float* Wi    = (const float*)d_in[4];
    const float* bi    = (const float*)d_in[5];
    const float* Wt    = (const float*)d_in[6];
    const float* bt    = (const float*)d_in[7];
    const float* convW = (const float*)d_in[8];
    const float* convb = (const float*)d_in[9];
    const void*  edge     = d_in[10];
    const void*  img_idx  = d_in[11];
    const float* img_vals = (const float*)d_in[12];
    const void*  txt_idx  = d_in[13];
    const float* txt_vals = (const float*)d_in[14];
    const void*  mm_idx   = d_in[15];
    const float* mm_vals  = (const float*)d_in[16];
    float* out = (float*)d_out;

    void *p_vemb, *p_temb, *p_hmm, *p_h1, *p_h2, *p_ego, *p_next, *p_hbuf, *p_cnt;
    cudaGetSymbolAddress(&p_vemb, g_vemb);
    cudaGetSymbolAddress(&p_temb, g_temb);
    cudaGetSymbolAddress(&p_hmm,  g_hmm);
    cudaGetSymbolAddress(&p_h1,   g_h1);
    cudaGetSymbolAddress(&p_h2,   g_h2);
    cudaGetSymbolAddress(&p_ego,  g_ego);
    cudaGetSymbolAddress(&p_next, g_next);
    cudaGetSymbolAddress(&p_hbuf, g_hbuf);
    cudaGetSymbolAddress(&p_cnt,  g_cnt);

    const int T = 256;
    const int gN   = (Nc + T - 1) / T;
    const int gNE  = (Nc * 64 + T - 1) / T;
    const int gEc  = (Ec + T - 1) / T;
    const int gE2  = (E2c + T - 1) / T;
    const int gEcM = Ec / 16;    // 16 lanes per edge (Ec % 16 == 0)
    const int gNW  = Nc / 8;     // warp per node

    // dtype detection
    k_detect<<<1, 256>>>(edge, 512, (long long)Nc, 0);
    k_detect<<<1, 256>>>(mm_idx, 512, (long long)NIc, 1);

    // edge conversion + CSR build (topology shared by all layers/propagations)
    k_zero_i32<<<gN, T>>>((int*)p_cnt, Nc);
    k_convert<<<gEc, T>>>(edge);
    k_scan<<<1, 1024>>>();
    k_copy_fill<<<gN, T>>>();
    k_fill<<<gEc, T>>>();

    // feature projections
    k_gemm64<<<NIc / 64, T>>>(vfeat, Wi, bi, (float*)p_vemb, 1024);
    k_gemm64<<<NIc / 64, T>>>(tfeat, Wt, bt, (float*)p_temb, 384);

    // KNN-graph SPMMs + L2 norms
    k_zero_f32<<<(NIc * 64 + T - 1) / T, T>>>((float*)p_hmm, NIc * 64);
    k_zero_f32<<<(NIc * 64 + T - 1) / T, T>>>((float*)p_h1,  NIc * 64);
    k_zero_f32<<<(NIc * 64 + T - 1) / T, T>>>((float*)p_h2,  NIc * 64);
    k_spmm<<<(NE_MM  * 16 + T - 1) / T, T>>>(mm_idx,  mm_vals,  item,           (float*)p_hmm, NE_MM,  1);
    k_spmm<<<(NE_IMG * 16 + T - 1) / T, T>>>(img_idx, img_vals, (float*)p_vemb, (float*)p_h1,  NE_IMG, 1);
    k_spmm<<<(NE_TXT * 16 + T - 1) / T, T>>>(txt_idx, txt_vals, (float*)p_temb, (float*)p_h2,  NE_TXT, 1);
    k_l2norm<<<(NIc * 32 + T - 1) / T, T>>>((float*)p_hmm, NIc);
    k_l2norm<<<(NIc * 32 + T - 1) / T, T>>>((float*)p_h1,  NIc);
    k_l2norm<<<(NIc * 32 + T - 1) / T, T>>>((float*)p_h2,  NIc);

    // three 2-layer GCN propagations
    struct Prop { const float* itemsrc; int filtered; int colbase; const float* addbuf; };
    Prop props[3] = {
        { (const float*)p_vemb, 1,  64, (const float*)p_h1 },
        { (const float*)p_temb, 1, 128, (const float*)p_h2 },
        { item,                 0,   0, (const float*)p_hmm },
    };
    for (int p = 0; p < 3; p++) {
        k_init_ego<<<gNE, T>>>(user, props[p].itemsrc);
        float* ego = (float*)p_ego;
        float* nxt = (float*)p_next;
        for (int l = 0; l < 2; l++) {
            if (props[p].filtered) {
                k_mask<<<gEcM, T>>>(ego);
                k_dinv_csr<<<gNW, T>>>(1);
                k_edge_w<<<gE2, T>>>(1);
            } else if (l == 0) {
                // unfiltered dinv / edge weights are layer-invariant
                k_dinv_csr<<<gNW, T>>>(0);
                k_edge_w<<<gE2, T>>>(0);
            }
            k_gemm64<<<Nc / 64, T>>>(ego, convW + (size_t)l * 64 * 64, nullptr,
                                     (float*)p_hbuf, 64);
            k_gcn_gather<<<gNW, T>>>(convb + (size_t)l * 64, nxt);
            float* t2 = ego; ego = nxt; nxt = t2;
        }
        k_writer<<<gNE, T>>>(props[p].addbuf, out, props[p].colbase);
    }
}